// round 2
// baseline (speedup 1.0000x reference)
#include <cuda_runtime.h>
#include <math.h>

// ---------------------------------------------------------------------------
// Problem constants
// ---------------------------------------------------------------------------
#define BB   128
#define NN   64
#define EE   128
#define NNODE (BB*NN)          // 8192
#define NEDGE (NN-1)           // 63

// ---------------------------------------------------------------------------
// Device scratch (static, no allocation)
// ---------------------------------------------------------------------------
__device__ float g_H  [NNODE*128];   // hidden after W1
__device__ float g_CAT[NNODE*256];   // [ae | attn_out]
__device__ float g_PP [NNODE*256];   // [P1 | Pa]
__device__ float g_D1 [NNODE*256];   // hidden after Wd1
__device__ float g_Wpp[256*128];     // rows 0..127: Wh1[:, :128]; rows 128..255: Wa1[:, :128]@Wq
__device__ float g_bpp[256];         // [bh1 | ba1]
__device__ float g_Wc [2*128];       // Whe @ Wh2
__device__ float g_bc [2];           // Whe @ bh2 + bhe
__device__ float g_Wh1e[128*8];      // Wh1[:, 128:135], padded to 8
__device__ float g_Wa1e[128*8];      // Wa1[:, 128:135], padded to 8
__device__ float g_ent[NNODE];

// ---------------------------------------------------------------------------
// Generic fused GEMM:  C = act(A @ W^T + bias)
// A: M x K (row stride lda), W: N x K (row stride ldw), C: M x N (row stride ldc)
// act: 0 = none, 1 = leaky_relu(0.01)
// M % 64 == 0, N % 64 == 0 assumed.
// ---------------------------------------------------------------------------
__global__ __launch_bounds__(256) void gemm_act(
    const float* __restrict__ A, int lda,
    const float* __restrict__ W, int ldw,
    const float* __restrict__ bias,
    float* __restrict__ C, int ldc,
    int M, int N, int K, int act)
{
    __shared__ float As[64][17];
    __shared__ float Ws[64][17];
    const int tid = threadIdx.x;
    const int bm = blockIdx.y * 64;
    const int bn = blockIdx.x * 64;
    const int tm = (tid >> 4) << 2;   // 0..60
    const int tn = (tid & 15) << 2;   // 0..60

    float acc[4][4];
#pragma unroll
    for (int i = 0; i < 4; i++)
#pragma unroll
        for (int j = 0; j < 4; j++) acc[i][j] = 0.f;

    for (int k0 = 0; k0 < K; k0 += 16) {
#pragma unroll
        for (int i = tid; i < 1024; i += 256) {
            int r = i >> 4, kk = i & 15;
            int kg = k0 + kk;
            As[r][kk] = (kg < K) ? A[(size_t)(bm + r) * lda + kg] : 0.f;
            Ws[r][kk] = (kg < K) ? W[(size_t)(bn + r) * ldw + kg] : 0.f;
        }
        __syncthreads();
#pragma unroll
        for (int kk = 0; kk < 16; kk++) {
            float a[4], w[4];
#pragma unroll
            for (int i = 0; i < 4; i++) a[i] = As[tm + i][kk];
#pragma unroll
            for (int j = 0; j < 4; j++) w[j] = Ws[tn + j][kk];
#pragma unroll
            for (int i = 0; i < 4; i++)
#pragma unroll
                for (int j = 0; j < 4; j++) acc[i][j] += a[i] * w[j];
        }
        __syncthreads();
    }

#pragma unroll
    for (int i = 0; i < 4; i++)
#pragma unroll
        for (int j = 0; j < 4; j++) {
            float v = acc[i][j];
            if (bias) v += bias[bn + tn + j];
            if (act == 1) v = (v > 0.f) ? v : 0.01f * v;
            C[(size_t)(bm + tm + i) * ldc + (bn + tn + j)] = v;
        }
}

// ---------------------------------------------------------------------------
// Precompute folded weights (runs every launch; deterministic, ~2 MFLOP)
// blocks 0..127 : Wpp rows 0..127   = Wh1[:, :128]
// blocks 128..255: Wpp rows 128..255 = Wa1[:, :128] @ Wq
// block 256     : Wc, bc, bpp, Wh1e, Wa1e
// ---------------------------------------------------------------------------
__global__ void precompute(
    const float* __restrict__ Wh1, const float* __restrict__ Wa1,
    const float* __restrict__ Wq,  const float* __restrict__ Whe,
    const float* __restrict__ Wh2, const float* __restrict__ bh2,
    const float* __restrict__ bhe, const float* __restrict__ bh1,
    const float* __restrict__ ba1)
{
    const int b = blockIdx.x, t = threadIdx.x;   // 128 threads
    if (b < 128) {
        g_Wpp[b * 128 + t] = Wh1[b * 135 + t];
    } else if (b < 256) {
        const int o = b - 128;
        float acc = 0.f;
        for (int j = 0; j < 128; j++) acc += Wa1[o * 135 + j] * Wq[j * 128 + t];
        g_Wpp[b * 128 + t] = acc;
    } else {
        float a0 = 0.f, a1 = 0.f;
        for (int j = 0; j < 128; j++) {
            a0 += Whe[j]       * Wh2[j * 128 + t];
            a1 += Whe[128 + j] * Wh2[j * 128 + t];
        }
        g_Wc[t] = a0; g_Wc[128 + t] = a1;
        if (t < 2) {
            float s = 0.f;
            for (int j = 0; j < 128; j++) s += Whe[t * 128 + j] * bh2[j];
            g_bc[t] = s + bhe[t];
        }
        g_bpp[t] = bh1[t]; g_bpp[128 + t] = ba1[t];
#pragma unroll
        for (int j = 0; j < 8; j++) {
            g_Wh1e[t * 8 + j] = (j < 7) ? Wh1[t * 135 + 128 + j] : 0.f;
            g_Wa1e[t * 8 + j] = (j < 7) ? Wa1[t * 135 + 128 + j] : 0.f;
        }
    }
}

// ---------------------------------------------------------------------------
// Fused per-edge kernel: one block (64 threads) per node.
// Computes edge features, hard-gate logits (via folded Wc), attention scores,
// gumbel softmax, masked softmax, combined weights, entropy, and attn_out
// (via the linearity trick: attn_out = Wv @ (sum c_k e_k) + bv * sum c_k).
// ---------------------------------------------------------------------------
__global__ __launch_bounds__(64) void edge_kernel(
    const float* __restrict__ emb,   // (8192, 9)
    const float* __restrict__ gum,   // (8192, 63, 2)
    const float* __restrict__ Wa2,   // (1,128)
    const float* __restrict__ ba2,   // (1,)
    const float* __restrict__ Wv,    // (128,7)
    const float* __restrict__ bv,    // (128,)
    float* __restrict__ out_log,
    float* __restrict__ out_dist,
    float* __restrict__ out_hw,
    float* __restrict__ out_cmb)
{
    __shared__ float P1s[128], Pas[128], Wc0s[128], Wc1s[128], Wa2s[128];
    __shared__ float Wh1e_s[128 * 8], Wa1e_s[128 * 8];
    __shared__ float s_e[64 * 8];
    __shared__ float s_sc[64], s_msk[64], s_ex[64], s_cmb[64];
    __shared__ float s_red[12];  // [0]=max [1]=den [2]=any [3]=csum [4..10]=esum

    const int node = blockIdx.x;
    const int n = node & (NN - 1);
    const int t = threadIdx.x;

    for (int i = t; i < 128; i += 64) {
        P1s[i]  = g_PP[(size_t)node * 256 + i];
        Pas[i]  = g_PP[(size_t)node * 256 + 128 + i];
        Wc0s[i] = g_Wc[i];
        Wc1s[i] = g_Wc[128 + i];
        Wa2s[i] = Wa2[i];
    }
    for (int i = t; i < 1024; i += 64) {
        Wh1e_s[i] = g_Wh1e[i];
        Wa1e_s[i] = g_Wa1e[i];
    }
    __syncthreads();

    const float* er = emb + (size_t)node * 9;
    const float pnx = er[0], pny = er[1], hnx = er[2], hny = er[3];

    float e[8];
    const bool active = (t < NEDGE);
    if (active) {
        const int j = t + (t >= n);
        const float* ej = emb + (size_t)(node - n + j) * 9;
        float dx = ej[0] - pnx, dy = ej[1] - pny;
        float sq = dx * dx + dy * dy;
        float rd = (sq > 0.f) ? sqrtf(sq) : 0.f;
        float ang = atan2f(dy, dx) - atan2f(hny, hnx);
        float ca, sa;
        sincosf(ang, &sa, &ca);
        e[0] = rd; e[1] = ca; e[2] = sa;
        e[3] = ej[2]; e[4] = ej[3]; e[5] = ej[7]; e[6] = ej[8];
        e[7] = 0.f;

        float l0 = 0.f, l1 = 0.f, sc = 0.f;
#pragma unroll 4
        for (int o = 0; o < 128; o++) {
            const float* wh = &Wh1e_s[o * 8];
            const float* wa = &Wa1e_s[o * 8];
            float h = P1s[o], a = Pas[o];
#pragma unroll
            for (int q = 0; q < 7; q++) { h += wh[q] * e[q]; a += wa[q] * e[q]; }
            h = (h > 0.f) ? h : 0.f;
            a = (a > 0.f) ? a : 0.f;
            l0 += Wc0s[o] * h;
            l1 += Wc1s[o] * h;
            sc += Wa2s[o] * a;
        }
        l0 += g_bc[0]; l1 += g_bc[1]; sc += ba2[0];

        const size_t gi = ((size_t)node * NEDGE + t) * 2;
        float g0 = gum[gi], g1 = gum[gi + 1];
        float y1 = 1.f / (1.f + expf(2.f * ((l0 + g0) - (l1 + g1))));

        const size_t oi = (size_t)node * NEDGE + t;
        out_log[oi]  = l1;
        out_dist[oi] = 12.f * rd;
        out_hw[oi]   = y1;

        s_msk[t] = (y1 > 0.5f) ? 1.f : 0.f;
        s_sc[t]  = sc;
#pragma unroll
        for (int q = 0; q < 8; q++) s_e[t * 8 + q] = e[q];
    }
    __syncthreads();

    if (t == 0) {  // deterministic serial max over masked scores
        float maxv = -1e30f, any = 0.f;
        for (int k = 0; k < NEDGE; k++)
            if (s_msk[k] > 0.f) { any = 1.f; if (s_sc[k] > maxv) maxv = s_sc[k]; }
        s_red[0] = maxv; s_red[2] = any;
    }
    __syncthreads();
    const float maxv = s_red[0], any = s_red[2];
    if (active) s_ex[t] = (s_msk[t] > 0.f) ? expf(s_sc[t] - maxv) : 0.f;
    __syncthreads();
    if (t == 0) {
        float den = 0.f;
        for (int k = 0; k < NEDGE; k++) den += s_ex[k];
        s_red[1] = den;
    }
    __syncthreads();
    const float den = s_red[1];
    if (active) {
        float c = (any > 0.f && s_msk[t] > 0.f) ? s_ex[t] / den : 0.f;
        s_cmb[t] = c;
        out_cmb[(size_t)node * NEDGE + t] = c;
    }
    __syncthreads();
    if (t < 8) {
        float s = 0.f;
        if (t < 7) {
            for (int k = 0; k < NEDGE; k++) s += s_cmb[k] * s_e[k * 8 + t];
            s_red[4 + t] = s;
        } else {
            for (int k = 0; k < NEDGE; k++) s += s_cmb[k];
            s_red[3] = s;
        }
    }
    __syncthreads();
    const float csum = s_red[3];
    if (t == 0) {
        float ent = 0.f;
        const float inv = 1.f / (csum + 1e-6f);
        for (int k = 0; k < NEDGE; k++) {
            float cw = s_cmb[k] * inv;
            ent -= cw * logf(cw + 1e-6f);
        }
        g_ent[node] = ent;
    }
    // attn_out = Wv @ esum + bv * csum  -> CAT[:, 128:256]
    for (int d = t; d < 128; d += 64) {
        float v = bv[d] * csum;
#pragma unroll
        for (int q = 0; q < 7; q++) v += Wv[d * 7 + q] * s_red[4 + q];
        g_CAT[(size_t)node * 256 + 128 + d] = v;
    }
}

// ---------------------------------------------------------------------------
// Deterministic entropy mean reduction
// ---------------------------------------------------------------------------
__global__ void ent_reduce(float* __restrict__ out_ent)
{
    __shared__ float s[256];
    const int t = threadIdx.x;
    float a = 0.f;
    for (int i = t; i < NNODE; i += 256) a += g_ent[i];
    s[t] = a;
    __syncthreads();
    for (int off = 128; off > 0; off >>= 1) {
        if (t < off) s[t] += s[t + off];
        __syncthreads();
    }
    if (t == 0) out_ent[0] = s[0] / (float)NNODE;
}

// ---------------------------------------------------------------------------
// Host launch
// ---------------------------------------------------------------------------
extern "C" void kernel_launch(void* const* d_in, const int* in_sizes, int n_in,
                              void* d_out, int out_size)
{
    const float* emb = (const float*)d_in[0];
    const float* gum = (const float*)d_in[1];
    const float* W1  = (const float*)d_in[2];
    const float* b1  = (const float*)d_in[3];
    const float* W2  = (const float*)d_in[4];
    const float* b2  = (const float*)d_in[5];
    const float* Wh1 = (const float*)d_in[6];
    const float* bh1 = (const float*)d_in[7];
    const float* Wh2 = (const float*)d_in[8];
    const float* bh2 = (const float*)d_in[9];
    const float* Whe = (const float*)d_in[10];
    const float* bhe = (const float*)d_in[11];
    const float* Wq  = (const float*)d_in[12];
    const float* Wa1 = (const float*)d_in[13];
    const float* ba1 = (const float*)d_in[14];
    const float* Wa2 = (const float*)d_in[15];
    const float* ba2 = (const float*)d_in[16];
    const float* Wv  = (const float*)d_in[17];
    const float* bv  = (const float*)d_in[18];
    const float* Wd1 = (const float*)d_in[19];
    const float* bd1 = (const float*)d_in[20];
    const float* Wd2 = (const float*)d_in[21];
    const float* bd2 = (const float*)d_in[22];

    float* out      = (float*)d_out;
    float* out_att  = out;                      // 8192*256
    float* out_log  = out_att + 2097152;        // 8192*63
    float* out_dist = out_log + 516096;         // 8192*63
    float* out_ent  = out_dist + 516096;        // 1
    float* out_hw   = out_ent + 1;              // 8192*63
    float* out_cmb  = out_hw + 516096;          // 8192*63

    float *H, *CAT, *PP, *D1, *Wpp, *bpp;
    cudaGetSymbolAddress((void**)&H,   g_H);
    cudaGetSymbolAddress((void**)&CAT, g_CAT);
    cudaGetSymbolAddress((void**)&PP,  g_PP);
    cudaGetSymbolAddress((void**)&D1,  g_D1);
    cudaGetSymbolAddress((void**)&Wpp, g_Wpp);
    cudaGetSymbolAddress((void**)&bpp, g_bpp);

    // Folded weights (must precede G3 + edge kernel)
    precompute<<<257, 128>>>(Wh1, Wa1, Wq, Whe, Wh2, bh2, bhe, bh1, ba1);

    // Node pipeline
    // G1: H = lrelu(embed @ W1^T + b1); embed = embedding[:, 4:9] (lda=9, ptr+4)
    gemm_act<<<dim3(2, 128), 256>>>(emb + 4, 9, W1, 5, b1, H, 128, NNODE, 128, 5, 1);
    // G2: AE = lrelu(H @ W2^T + b2) -> CAT[:, :128]
    gemm_act<<<dim3(2, 128), 256>>>(H, 128, W2, 128, b2, CAT, 256, NNODE, 128, 128, 1);
    // G3: [P1 | Pa] = AE @ Wpp^T + bpp
    gemm_act<<<dim3(4, 128), 256>>>(CAT, 256, Wpp, 128, bpp, PP, 256, NNODE, 256, 128, 0);

    // Edge pipeline (writes 4 output regions + CAT[:, 128:])
    edge_kernel<<<NNODE, 64>>>(emb, gum, Wa2, ba2, Wv, bv,
                               out_log, out_dist, out_hw, out_cmb);

    ent_reduce<<<1, 256>>>(out_ent);

    // Decoder
    gemm_act<<<dim3(4, 128), 256>>>(CAT, 256, Wd1, 256, bd1, D1, 256, NNODE, 256, 256, 1);
    gemm_act<<<dim3(4, 128), 256>>>(D1, 256, Wd2, 256, bd2, out_att, 256, NNODE, 256, 256, 1);

    (void)in_sizes; (void)n_in; (void)out_size;
}